// round 4
// baseline (speedup 1.0000x reference)
#include <cuda_runtime.h>
#include <math.h>

#define BSZ   2
#define SEQ   2048
#define HID   1024
#define HEADS 16
#define HD    64
#define QBLK  64
#define M_TOT (BSZ*SEQ)

// Scratch (allocation-free): Q, K, V, attention output — 16 MB each.
__device__ float g_Q[(size_t)M_TOT * HID];
__device__ float g_K[(size_t)M_TOT * HID];
__device__ float g_V[(size_t)M_TOT * HID];
__device__ float g_A[(size_t)M_TOT * HID];

// ---------------------------------------------------------------------------
// C[m,n] = sum_k A[m,k] * B[n,k] + bias[n]      (i.e. C = A @ B^T + bias)
// Tile: 128x128 output per CTA, BK=16, 256 threads, 8x8 micro-tile/thread.
// Column mapping n = n0 + tx + 16*j (strided) keeps Bs reads <=2-way conflicted.
// ---------------------------------------------------------------------------
__global__ __launch_bounds__(256) void gemm_bias_kernel(
    const float* __restrict__ A, const float* __restrict__ B,
    const float* __restrict__ bias, float* __restrict__ C,
    int M, int N, int K)
{
    __shared__ float As[128][20];
    __shared__ float Bs[128][20];

    const int tid = threadIdx.x;
    const int tx  = tid & 15;
    const int ty  = tid >> 4;
    const int m0  = blockIdx.y * 128;
    const int n0  = blockIdx.x * 128;
    const int lr  = tid >> 2;          // 0..63  (load row)
    const int lc  = (tid & 3) * 4;     // 0,4,8,12 (load col within BK=16)

    float acc[8][8];
    #pragma unroll
    for (int i = 0; i < 8; i++)
        #pragma unroll
        for (int j = 0; j < 8; j++) acc[i][j] = 0.f;

    const float* Ab = A + (size_t)m0 * K;
    const float* Bb = B + (size_t)n0 * K;

    for (int k0 = 0; k0 < K; k0 += 16) {
        #pragma unroll
        for (int t = 0; t < 2; t++) {
            int r = lr + t * 64;
            *(float4*)(&As[r][lc]) = *(const float4*)(Ab + (size_t)r * K + k0 + lc);
            *(float4*)(&Bs[r][lc]) = *(const float4*)(Bb + (size_t)r * K + k0 + lc);
        }
        __syncthreads();
        #pragma unroll
        for (int k = 0; k < 16; k++) {
            float a[8], b[8];
            #pragma unroll
            for (int i = 0; i < 8; i++) a[i] = As[ty * 8 + i][k];
            #pragma unroll
            for (int j = 0; j < 8; j++) b[j] = Bs[tx + 16 * j][k];
            #pragma unroll
            for (int i = 0; i < 8; i++)
                #pragma unroll
                for (int j = 0; j < 8; j++)
                    acc[i][j] = fmaf(a[i], b[j], acc[i][j]);
        }
        __syncthreads();
    }

    #pragma unroll
    for (int i = 0; i < 8; i++) {
        int m = m0 + ty * 8 + i;
        float* Crow = C + (size_t)m * N;
        #pragma unroll
        for (int j = 0; j < 8; j++) {
            int n = n0 + tx + 16 * j;
            Crow[n] = acc[i][j] + bias[n];
        }
    }
}

// ---------------------------------------------------------------------------
// Flash attention over one (batch, head, q-block) per CTA.
// Q/K/V layout: [b, s, h*64 + d]. Block-causal: kv block kb in [0, qb].
// 64x64 tiles; 256 threads; thread (ty,tx) owns rows ty*4+i, cols tx+16*j.
// ---------------------------------------------------------------------------
#define APAD 68   // row stride (floats): 64 + 4 pad, keeps float4 alignment

__global__ __launch_bounds__(256) void attn_kernel(
    const float* __restrict__ Q, const float* __restrict__ K,
    const float* __restrict__ V, float* __restrict__ O)
{
    extern __shared__ float sm[];
    float (*Qs)[APAD] = (float (*)[APAD])(sm);
    float (*Ks)[APAD] = (float (*)[APAD])(sm + 64 * APAD);
    float (*Vs)[APAD] = (float (*)[APAD])(sm + 2 * 64 * APAD);
    float (*Ps)[APAD] = (float (*)[APAD])(sm + 3 * 64 * APAD);

    const int tid = threadIdx.x;
    const int tx  = tid & 15;
    const int ty  = tid >> 4;
    const int qb  = blockIdx.x;
    const int h   = blockIdx.y;
    const int b   = blockIdx.z;
    const int q0  = qb * QBLK;

    const size_t base = (size_t)b * SEQ * HID + (size_t)h * HD;

    // Load Q tile (64 rows x 64 dims)
    #pragma unroll
    for (int t = 0; t < 4; t++) {
        int idx = tid + t * 256;
        int r = idx >> 4;
        int c = (idx & 15) * 4;
        *(float4*)(&Qs[r][c]) =
            *(const float4*)(Q + base + (size_t)(q0 + r) * HID + c);
    }

    float m_i[4], l_i[4], o_acc[4][4];
    #pragma unroll
    for (int i = 0; i < 4; i++) {
        m_i[i] = -1e30f;
        l_i[i] = 0.f;
        #pragma unroll
        for (int j = 0; j < 4; j++) o_acc[i][j] = 0.f;
    }

    const float scale = 0.125f;   // 1/sqrt(64)

    for (int kb = 0; kb <= qb; kb++) {
        __syncthreads();   // previous iteration's Vs/Ps reads done
        #pragma unroll
        for (int t = 0; t < 4; t++) {
            int idx = tid + t * 256;
            int r = idx >> 4;
            int c = (idx & 15) * 4;
            size_t g = base + (size_t)(kb * QBLK + r) * HID + c;
            *(float4*)(&Ks[r][c]) = *(const float4*)(K + g);
            *(float4*)(&Vs[r][c]) = *(const float4*)(V + g);
        }
        __syncthreads();

        // S = Q @ K^T * scale   (thread: rows ty*4+i, cols tx+16*j)
        float s[4][4];
        #pragma unroll
        for (int i = 0; i < 4; i++)
            #pragma unroll
            for (int j = 0; j < 4; j++) s[i][j] = 0.f;

        #pragma unroll 8
        for (int d = 0; d < 64; d++) {
            float qv[4], kv[4];
            #pragma unroll
            for (int i = 0; i < 4; i++) qv[i] = Qs[ty * 4 + i][d];
            #pragma unroll
            for (int j = 0; j < 4; j++) kv[j] = Ks[tx + 16 * j][d];
            #pragma unroll
            for (int i = 0; i < 4; i++)
                #pragma unroll
                for (int j = 0; j < 4; j++)
                    s[i][j] = fmaf(qv[i], kv[j], s[i][j]);
        }

        // Online softmax per row (row group = 16 contiguous lanes in a warp)
        #pragma unroll
        for (int i = 0; i < 4; i++) {
            float mx = -1e30f;
            #pragma unroll
            for (int j = 0; j < 4; j++) {
                s[i][j] *= scale;
                mx = fmaxf(mx, s[i][j]);
            }
            #pragma unroll
            for (int off = 8; off >= 1; off >>= 1)
                mx = fmaxf(mx, __shfl_xor_sync(0xffffffffu, mx, off));

            float mnew = fmaxf(m_i[i], mx);
            float corr = __expf(m_i[i] - mnew);
            m_i[i] = mnew;

            float rs = 0.f;
            #pragma unroll
            for (int j = 0; j < 4; j++) {
                s[i][j] = __expf(s[i][j] - mnew);
                rs += s[i][j];
            }
            #pragma unroll
            for (int off = 8; off >= 1; off >>= 1)
                rs += __shfl_xor_sync(0xffffffffu, rs, off);

            l_i[i] = l_i[i] * corr + rs;
            #pragma unroll
            for (int j = 0; j < 4; j++) o_acc[i][j] *= corr;
            #pragma unroll
            for (int j = 0; j < 4; j++) Ps[ty * 4 + i][tx + 16 * j] = s[i][j];
        }
        __syncthreads();

        // O += P @ V   (thread dims: tx+16*j)
        #pragma unroll 4
        for (int jl = 0; jl < 64; jl++) {
            float p[4], v[4];
            #pragma unroll
            for (int i = 0; i < 4; i++) p[i] = Ps[ty * 4 + i][jl];
            #pragma unroll
            for (int j = 0; j < 4; j++) v[j] = Vs[jl][tx + 16 * j];
            #pragma unroll
            for (int i = 0; i < 4; i++)
                #pragma unroll
                for (int j = 0; j < 4; j++)
                    o_acc[i][j] = fmaf(p[i], v[j], o_acc[i][j]);
        }
    }

    // Epilogue: O /= l, write to [b, s, h*64 + d]
    #pragma unroll
    for (int i = 0; i < 4; i++) {
        float inv = 1.f / l_i[i];
        size_t row = base + (size_t)(q0 + ty * 4 + i) * HID;
        #pragma unroll
        for (int j = 0; j < 4; j++)
            O[row + tx + 16 * j] = o_acc[i][j] * inv;
    }
}

// ---------------------------------------------------------------------------

extern "C" void kernel_launch(void* const* d_in, const int* in_sizes, int n_in,
                              void* d_out, int out_size)
{
    (void)in_sizes; (void)n_in; (void)out_size;

    const float* X  = (const float*)d_in[0];
    const float* Wq = (const float*)d_in[1];
    const float* bq = (const float*)d_in[2];
    const float* Wk = (const float*)d_in[3];
    const float* bk = (const float*)d_in[4];
    const float* Wv = (const float*)d_in[5];
    const float* bv = (const float*)d_in[6];
    const float* Wo = (const float*)d_in[7];
    const float* bo = (const float*)d_in[8];

    float *Q, *K, *V, *A;
    cudaGetSymbolAddress((void**)&Q, g_Q);
    cudaGetSymbolAddress((void**)&K, g_K);
    cudaGetSymbolAddress((void**)&V, g_V);
    cudaGetSymbolAddress((void**)&A, g_A);

    dim3 gg(HID / 128, M_TOT / 128);   // (8, 32)

    gemm_bias_kernel<<<gg, 256>>>(X, Wq, bq, Q, M_TOT, HID, HID);
    gemm_bias_kernel<<<gg, 256>>>(X, Wk, bk, K, M_TOT, HID, HID);
    gemm_bias_kernel<<<gg, 256>>>(X, Wv, bv, V, M_TOT, HID, HID);

    const int smem = 4 * 64 * APAD * (int)sizeof(float);   // 69632 B
    cudaFuncSetAttribute(attn_kernel,
                         cudaFuncAttributeMaxDynamicSharedMemorySize, smem);
    attn_kernel<<<dim3(SEQ / QBLK, HEADS, BSZ), 256, smem>>>(Q, K, V, A);

    gemm_bias_kernel<<<gg, 256>>>(A, Wo, bo, (float*)d_out, M_TOT, HID, HID);
}

// round 6
// speedup vs baseline: 1.8064x; 1.8064x over previous
#include <cuda_runtime.h>
#include <cstdint>
#include <math.h>

#define BSZ   2
#define SEQ   2048
#define HID   1024
#define HEADS 16
#define HD    64
#define QBLK  64
#define M_TOT (BSZ*SEQ)

// Scratch (allocation-free): Q, K, V, attention output — 16 MB each.
__device__ float g_Q[(size_t)M_TOT * HID];
__device__ float g_K[(size_t)M_TOT * HID];
__device__ float g_V[(size_t)M_TOT * HID];
__device__ float g_A[(size_t)M_TOT * HID];

__device__ __forceinline__ uint32_t smem_u32(const void* p) {
    uint32_t a;
    asm("{ .reg .u64 t; cvta.to.shared.u64 t, %1; cvt.u32.u64 %0, t; }"
        : "=r"(a) : "l"(p));
    return a;
}

__device__ __forceinline__ uint32_t f2tf32(float v) {
    uint32_t r;
    asm("cvt.rna.tf32.f32 %0, %1;" : "=r"(r) : "f"(v));
    return r;
}

__device__ __forceinline__ void mma_tf32(
    float& c0, float& c1, float& c2, float& c3,
    uint32_t a0, uint32_t a1, uint32_t a2, uint32_t a3,
    uint32_t b0, uint32_t b1)
{
    asm volatile(
        "mma.sync.aligned.m16n8k8.row.col.f32.tf32.tf32.f32 "
        "{%0,%1,%2,%3}, {%4,%5,%6,%7}, {%8,%9}, {%0,%1,%2,%3};"
        : "+f"(c0), "+f"(c1), "+f"(c2), "+f"(c3)
        : "r"(a0), "r"(a1), "r"(a2), "r"(a3), "r"(b0), "r"(b1));
}

// ===========================================================================
// HMMA tf32 GEMM: C[m,n] = sum_k A[m,k]*B[n,k] + bias[n]     (C = A@B^T + b)
// CTA 128x128, BK=16, cp.async double-buffer, 8 warps x (64x32) sub-tiles.
// ===========================================================================
#define TM 128
#define TN 128
#define BK 16
#define SPAD 20   // smem row stride (floats); fragment loads conflict-free

__global__ __launch_bounds__(256) void gemm_tc(
    const float* __restrict__ A, const float* __restrict__ B,
    const float* __restrict__ bias, float* __restrict__ C,
    int M, int N, int K)
{
    __shared__ float As[2][TM][SPAD];
    __shared__ float Bs[2][TN][SPAD];

    const int tid  = threadIdx.x;
    const int wid  = tid >> 5;
    const int lane = tid & 31;
    const int g    = lane >> 2;     // groupID (0..7)
    const int t    = lane & 3;      // thread-in-group (0..3)
    const int m0   = blockIdx.y * TM;
    const int n0   = blockIdx.x * TN;
    const int moff = (wid & 1) * 64;   // warp m offset
    const int noff = (wid >> 1) * 32;  // warp n offset
    const int NK   = K / BK;

    // Load indexing: 2 float4 per thread per array per stage
    const int lr = tid >> 2;          // 0..63
    const int lc = (tid & 3) * 4;     // 0,4,8,12

    const float* Ab = A + (size_t)m0 * K;
    const float* Bb = B + (size_t)n0 * K;

    float acc[4][4][4];
    #pragma unroll
    for (int i = 0; i < 4; i++)
        #pragma unroll
        for (int j = 0; j < 4; j++)
            #pragma unroll
            for (int r = 0; r < 4; r++) acc[i][j][r] = 0.f;

    // ---- async load of one BK-chunk into stage s ----
    auto load_stage = [&](int kc, int s) {
        const float* Ag = Ab + kc * BK;
        const float* Bg = Bb + kc * BK;
        #pragma unroll
        for (int i = 0; i < 2; i++) {
            int r = lr + i * 64;
            uint32_t da = smem_u32(&As[s][r][lc]);
            uint32_t db = smem_u32(&Bs[s][r][lc]);
            asm volatile("cp.async.cg.shared.global [%0], [%1], 16;"
                         :: "r"(da), "l"(Ag + (size_t)r * K + lc));
            asm volatile("cp.async.cg.shared.global [%0], [%1], 16;"
                         :: "r"(db), "l"(Bg + (size_t)r * K + lc));
        }
        asm volatile("cp.async.commit_group;");
    };

    load_stage(0, 0);

    for (int kc = 0; kc < NK; kc++) {
        const int s = kc & 1;
        if (kc + 1 < NK) {
            load_stage(kc + 1, s ^ 1);
            asm volatile("cp.async.wait_group 1;");
        } else {
            asm volatile("cp.async.wait_group 0;");
        }
        __syncthreads();

        #pragma unroll
        for (int k8 = 0; k8 < BK; k8 += 8) {
            uint32_t a[4][4], b[4][2];
            #pragma unroll
            for (int mt = 0; mt < 4; mt++) {
                int row = moff + mt * 16;
                a[mt][0] = f2tf32(As[s][row + g    ][k8 + t    ]);
                a[mt][1] = f2tf32(As[s][row + g + 8][k8 + t    ]);
                a[mt][2] = f2tf32(As[s][row + g    ][k8 + t + 4]);
                a[mt][3] = f2tf32(As[s][row + g + 8][k8 + t + 4]);
            }
            #pragma unroll
            for (int nt = 0; nt < 4; nt++) {
                int col = noff + nt * 8;
                b[nt][0] = f2tf32(Bs[s][col + g][k8 + t    ]);
                b[nt][1] = f2tf32(Bs[s][col + g][k8 + t + 4]);
            }
            #pragma unroll
            for (int mt = 0; mt < 4; mt++)
                #pragma unroll
                for (int nt = 0; nt < 4; nt++)
                    mma_tf32(acc[mt][nt][0], acc[mt][nt][1],
                             acc[mt][nt][2], acc[mt][nt][3],
                             a[mt][0], a[mt][1], a[mt][2], a[mt][3],
                             b[nt][0], b[nt][1]);
        }
        __syncthreads();
    }

    // Epilogue: c0:(g,2t) c1:(g,2t+1) c2:(g+8,2t) c3:(g+8,2t+1)
    #pragma unroll
    for (int mt = 0; mt < 4; mt++) {
        int mrow0 = m0 + moff + mt * 16 + g;
        #pragma unroll
        for (int nt = 0; nt < 4; nt++) {
            int n = n0 + noff + nt * 8 + 2 * t;
            float b0 = __ldg(bias + n);
            float b1 = __ldg(bias + n + 1);
            float2 v0 = { acc[mt][nt][0] + b0, acc[mt][nt][1] + b1 };
            float2 v1 = { acc[mt][nt][2] + b0, acc[mt][nt][3] + b1 };
            *(float2*)(C + (size_t)mrow0 * N + n)       = v0;
            *(float2*)(C + (size_t)(mrow0 + 8) * N + n) = v1;
        }
    }
}

// ---------------------------------------------------------------------------
// Flash attention (unchanged from passing R3 kernel)
// ---------------------------------------------------------------------------
#define APAD 68

__global__ __launch_bounds__(256) void attn_kernel(
    const float* __restrict__ Q, const float* __restrict__ K,
    const float* __restrict__ V, float* __restrict__ O)
{
    extern __shared__ float sm[];
    float (*Qs)[APAD] = (float (*)[APAD])(sm);
    float (*Ks)[APAD] = (float (*)[APAD])(sm + 64 * APAD);
    float (*Vs)[APAD] = (float (*)[APAD])(sm + 2 * 64 * APAD);
    float (*Ps)[APAD] = (float (*)[APAD])(sm + 3 * 64 * APAD);

    const int tid = threadIdx.x;
    const int tx  = tid & 15;
    const int ty  = tid >> 4;
    const int qb  = blockIdx.x;
    const int h   = blockIdx.y;
    const int b   = blockIdx.z;
    const int q0  = qb * QBLK;

    const size_t base = (size_t)b * SEQ * HID + (size_t)h * HD;

    #pragma unroll
    for (int t = 0; t < 4; t++) {
        int idx = tid + t * 256;
        int r = idx >> 4;
        int c = (idx & 15) * 4;
        *(float4*)(&Qs[r][c]) =
            *(const float4*)(Q + base + (size_t)(q0 + r) * HID + c);
    }

    float m_i[4], l_i[4], o_acc[4][4];
    #pragma unroll
    for (int i = 0; i < 4; i++) {
        m_i[i] = -1e30f;
        l_i[i] = 0.f;
        #pragma unroll
        for (int j = 0; j < 4; j++) o_acc[i][j] = 0.f;
    }

    const float scale = 0.125f;

    for (int kb = 0; kb <= qb; kb++) {
        __syncthreads();
        #pragma unroll
        for (int t = 0; t < 4; t++) {
            int idx = tid + t * 256;
            int r = idx >> 4;
            int c = (idx & 15) * 4;
            size_t gofs = base + (size_t)(kb * QBLK + r) * HID + c;
            *(float4*)(&Ks[r][c]) = *(const float4*)(K + gofs);
            *(float4*)(&Vs[r][c]) = *(const float4*)(V + gofs);
        }
        __syncthreads();

        float s[4][4];
        #pragma unroll
        for (int i = 0; i < 4; i++)
            #pragma unroll
            for (int j = 0; j < 4; j++) s[i][j] = 0.f;

        #pragma unroll 8
        for (int d = 0; d < 64; d++) {
            float qv[4], kv[4];
            #pragma unroll
            for (int i = 0; i < 4; i++) qv[i] = Qs[ty * 4 + i][d];
            #pragma unroll
            for (int j = 0; j < 4; j++) kv[j] = Ks[tx + 16 * j][d];
            #pragma unroll
            for (int i = 0; i < 4; i++)
                #pragma unroll
                for (int j = 0; j < 4; j++)
                    s[i][j] = fmaf(qv[i], kv[j], s[i][j]);
        }

        #pragma unroll
        for (int i = 0; i < 4; i++) {
            float mx = -1e30f;
            #pragma unroll
            for (int j = 0; j < 4; j++) {
                s[i][j] *= scale;
                mx = fmaxf(mx, s[i][j]);
            }
            #pragma unroll
            for (int off = 8; off >= 1; off >>= 1)
                mx = fmaxf(mx, __shfl_xor_sync(0xffffffffu, mx, off));

            float mnew = fmaxf(m_i[i], mx);
            float corr = __expf(m_i[i] - mnew);
            m_i[i] = mnew;

            float rs = 0.f;
            #pragma unroll
            for (int j = 0; j < 4; j++) {
                s[i][j] = __expf(s[i][j] - mnew);
                rs += s[i][j];
            }
            #pragma unroll
            for (int off = 8; off >= 1; off >>= 1)
                rs += __shfl_xor_sync(0xffffffffu, rs, off);

            l_i[i] = l_i[i] * corr + rs;
            #pragma unroll
            for (int j = 0; j < 4; j++) o_acc[i][j] *= corr;
            #pragma unroll
            for (int j = 0; j < 4; j++) Ps[ty * 4 + i][tx + 16 * j] = s[i][j];
        }
        __syncthreads();

        #pragma unroll 4
        for (int jl = 0; jl < 64; jl++) {
            float p[4], v[4];
            #pragma unroll
            for (int i = 0; i < 4; i++) p[i] = Ps[ty * 4 + i][jl];
            #pragma unroll
            for (int j = 0; j < 4; j++) v[j] = Vs[jl][tx + 16 * j];
            #pragma unroll
            for (int i = 0; i < 4; i++)
                #pragma unroll
                for (int j = 0; j < 4; j++)
                    o_acc[i][j] = fmaf(p[i], v[j], o_acc[i][j]);
        }
    }

    #pragma unroll
    for (int i = 0; i < 4; i++) {
        float inv = 1.f / l_i[i];
        size_t row = base + (size_t)(q0 + ty * 4 + i) * HID;
        #pragma unroll
        for (int j = 0; j < 4; j++)
            O[row + tx + 16 * j] = o_acc[i][j] * inv;
    }
}

// ---------------------------------------------------------------------------

extern "C" void kernel_launch(void* const* d_in, const int* in_sizes, int n_in,
                              void* d_out, int out_size)
{
    (void)in_sizes; (void)n_in; (void)out_size;

    const float* X  = (const float*)d_in[0];
    const float* Wq = (const float*)d_in[1];
    const float* bq = (const float*)d_in[2];
    const float* Wk = (const float*)d_in[3];
    const float* bk = (const float*)d_in[4];
    const float* Wv = (const float*)d_in[5];
    const float* bv = (const float*)d_in[6];
    const float* Wo = (const float*)d_in[7];
    const float* bo = (const float*)d_in[8];

    float *Q, *K, *V, *A;
    cudaGetSymbolAddress((void**)&Q, g_Q);
    cudaGetSymbolAddress((void**)&K, g_K);
    cudaGetSymbolAddress((void**)&V, g_V);
    cudaGetSymbolAddress((void**)&A, g_A);

    dim3 gg(HID / TN, M_TOT / TM);   // (8, 32)

    gemm_tc<<<gg, 256>>>(X, Wq, bq, Q, M_TOT, HID, HID);
    gemm_tc<<<gg, 256>>>(X, Wk, bk, K, M_TOT, HID, HID);
    gemm_tc<<<gg, 256>>>(X, Wv, bv, V, M_TOT, HID, HID);

    const int smem = 4 * 64 * APAD * (int)sizeof(float);   // 69632 B
    cudaFuncSetAttribute(attn_kernel,
                         cudaFuncAttributeMaxDynamicSharedMemorySize, smem);
    attn_kernel<<<dim3(SEQ / QBLK, HEADS, BSZ), 256, smem>>>(Q, K, V, A);

    gemm_tc<<<gg, 256>>>(A, Wo, bo, (float*)d_out, M_TOT, HID, HID);
}

// round 7
// speedup vs baseline: 2.7522x; 1.5236x over previous
#include <cuda_runtime.h>
#include <cstdint>
#include <math.h>

#define BSZ   2
#define SEQ   2048
#define HID   1024
#define HEADS 16
#define HD    64
#define QBLK  64
#define M_TOT (BSZ*SEQ)

// Scratch (allocation-free): Q, K, V, attention output — 16 MB each.
__device__ float g_Q[(size_t)M_TOT * HID];
__device__ float g_K[(size_t)M_TOT * HID];
__device__ float g_V[(size_t)M_TOT * HID];
__device__ float g_A[(size_t)M_TOT * HID];

__device__ __forceinline__ uint32_t smem_u32(const void* p) {
    uint32_t a;
    asm("{ .reg .u64 t; cvta.to.shared.u64 t, %1; cvt.u32.u64 %0, t; }"
        : "=r"(a) : "l"(p));
    return a;
}

__device__ __forceinline__ uint32_t f2tf32(float v) {
    uint32_t r;
    asm("cvt.rna.tf32.f32 %0, %1;" : "=r"(r) : "f"(v));
    return r;
}

__device__ __forceinline__ void mma_tf32(
    float& c0, float& c1, float& c2, float& c3,
    uint32_t a0, uint32_t a1, uint32_t a2, uint32_t a3,
    uint32_t b0, uint32_t b1)
{
    asm volatile(
        "mma.sync.aligned.m16n8k8.row.col.f32.tf32.tf32.f32 "
        "{%0,%1,%2,%3}, {%4,%5,%6,%7}, {%8,%9}, {%0,%1,%2,%3};"
        : "+f"(c0), "+f"(c1), "+f"(c2), "+f"(c3)
        : "r"(a0), "r"(a1), "r"(a2), "r"(a3), "r"(b0), "r"(b1));
}

// Fast exp on FMA/ALU pipes (no MUFU). Valid for x <= ~1; clamped below.
__device__ __forceinline__ float fexp(float x) {
    x = fmaxf(x, -87.0f);
    float y = x * 1.44269504088896f;          // log2(e)
    float z = y + 12582912.0f;                 // 1.5 * 2^23 magic
    float i = z - 12582912.0f;                 // round(y)
    float f = y - i;                           // [-0.5, 0.5]
    float p =            1.33335581e-3f;
    p = fmaf(p, f, 9.61812911e-3f);
    p = fmaf(p, f, 5.55041087e-2f);
    p = fmaf(p, f, 2.40226507e-1f);
    p = fmaf(p, f, 6.93147181e-1f);
    p = fmaf(p, f, 1.0f);
    float sc = __int_as_float((__float_as_int(z) << 23) + 0x3f800000);
    return sc * p;
}

// ===========================================================================
// HMMA tf32 GEMM (unchanged from passing R6): C = A@B^T + bias
// ===========================================================================
#define TM 128
#define TN 128
#define BK 16
#define SPAD 20

__global__ __launch_bounds__(256) void gemm_tc(
    const float* __restrict__ A, const float* __restrict__ B,
    const float* __restrict__ bias, float* __restrict__ C,
    int M, int N, int K)
{
    __shared__ float As[2][TM][SPAD];
    __shared__ float Bs[2][TN][SPAD];

    const int tid  = threadIdx.x;
    const int wid  = tid >> 5;
    const int lane = tid & 31;
    const int g    = lane >> 2;
    const int t    = lane & 3;
    const int m0   = blockIdx.y * TM;
    const int n0   = blockIdx.x * TN;
    const int moff = (wid & 1) * 64;
    const int noff = (wid >> 1) * 32;
    const int NK   = K / BK;

    const int lr = tid >> 2;
    const int lc = (tid & 3) * 4;

    const float* Ab = A + (size_t)m0 * K;
    const float* Bb = B + (size_t)n0 * K;

    float acc[4][4][4];
    #pragma unroll
    for (int i = 0; i < 4; i++)
        #pragma unroll
        for (int j = 0; j < 4; j++)
            #pragma unroll
            for (int r = 0; r < 4; r++) acc[i][j][r] = 0.f;

    auto load_stage = [&](int kc, int s) {
        const float* Ag = Ab + kc * BK;
        const float* Bg = Bb + kc * BK;
        #pragma unroll
        for (int i = 0; i < 2; i++) {
            int r = lr + i * 64;
            uint32_t da = smem_u32(&As[s][r][lc]);
            uint32_t db = smem_u32(&Bs[s][r][lc]);
            asm volatile("cp.async.cg.shared.global [%0], [%1], 16;"
                         :: "r"(da), "l"(Ag + (size_t)r * K + lc));
            asm volatile("cp.async.cg.shared.global [%0], [%1], 16;"
                         :: "r"(db), "l"(Bg + (size_t)r * K + lc));
        }
        asm volatile("cp.async.commit_group;");
    };

    load_stage(0, 0);

    for (int kc = 0; kc < NK; kc++) {
        const int s = kc & 1;
        if (kc + 1 < NK) {
            load_stage(kc + 1, s ^ 1);
            asm volatile("cp.async.wait_group 1;");
        } else {
            asm volatile("cp.async.wait_group 0;");
        }
        __syncthreads();

        #pragma unroll
        for (int k8 = 0; k8 < BK; k8 += 8) {
            uint32_t a[4][4], b[4][2];
            #pragma unroll
            for (int mt = 0; mt < 4; mt++) {
                int row = moff + mt * 16;
                a[mt][0] = f2tf32(As[s][row + g    ][k8 + t    ]);
                a[mt][1] = f2tf32(As[s][row + g + 8][k8 + t    ]);
                a[mt][2] = f2tf32(As[s][row + g    ][k8 + t + 4]);
                a[mt][3] = f2tf32(As[s][row + g + 8][k8 + t + 4]);
            }
            #pragma unroll
            for (int nt = 0; nt < 4; nt++) {
                int col = noff + nt * 8;
                b[nt][0] = f2tf32(Bs[s][col + g][k8 + t    ]);
                b[nt][1] = f2tf32(Bs[s][col + g][k8 + t + 4]);
            }
            #pragma unroll
            for (int mt = 0; mt < 4; mt++)
                #pragma unroll
                for (int nt = 0; nt < 4; nt++)
                    mma_tf32(acc[mt][nt][0], acc[mt][nt][1],
                             acc[mt][nt][2], acc[mt][nt][3],
                             a[mt][0], a[mt][1], a[mt][2], a[mt][3],
                             b[nt][0], b[nt][1]);
        }
        __syncthreads();
    }

    #pragma unroll
    for (int mt = 0; mt < 4; mt++) {
        int mrow0 = m0 + moff + mt * 16 + g;
        #pragma unroll
        for (int nt = 0; nt < 4; nt++) {
            int n = n0 + noff + nt * 8 + 2 * t;
            float b0 = __ldg(bias + n);
            float b1 = __ldg(bias + n + 1);
            float2 v0 = { acc[mt][nt][0] + b0, acc[mt][nt][1] + b1 };
            float2 v1 = { acc[mt][nt][2] + b0, acc[mt][nt][3] + b1 };
            *(float2*)(C + (size_t)mrow0 * N + n)       = v0;
            *(float2*)(C + (size_t)(mrow0 + 8) * N + n) = v1;
        }
    }
}

// ===========================================================================
// Tensor-core flash attention. One CTA = (b, h, q-block of 64). 4 warps.
// S = Q@K^T via mma (warp w: q rows 16w..16w+15, all 64 kv cols).
// PV computed as O^T = V^T @ P^T (warp w: d rows 16w..16w+15, all 64 q cols)
// so both B-fragments (K, P) read smem in natural [row][k] layout.
// Softmax in registers + FMA-pipe fexp; cross-warp corr/l via smem.
// ===========================================================================
#define AST 68                              // smem row stride (floats)
#define OFF_K   (64*AST)                    // Ks stage 0
#define OFF_V   (3*64*AST)                  // Vs stage 0
#define OFF_P   (5*64*AST)
#define OFF_CR  (6*64*AST)
#define OFF_LI  (6*64*AST + 64)
#define ATT_SMEM ((6*64*AST + 128) * 4)     // 104,960 B

__global__ __launch_bounds__(128) void attn_tc(
    const float* __restrict__ Qp, const float* __restrict__ Kp,
    const float* __restrict__ Vp, float* __restrict__ Op)
{
    extern __shared__ float sm[];
    const int tid  = threadIdx.x;
    const int wid  = tid >> 5;
    const int lane = tid & 31;
    const int g    = lane >> 2;
    const int t    = lane & 3;

    const int qb = (int)gridDim.x - 1 - (int)blockIdx.x;  // big tiles first
    const int h  = blockIdx.y;
    const int b  = blockIdx.z;
    const int q0 = qb * QBLK;
    const size_t base = (size_t)b * SEQ * HID + (size_t)h * HD;

    // Load Q tile: scaled by 1/8 and pre-rounded to tf32
    #pragma unroll
    for (int i = 0; i < 8; i++) {
        int idx = tid + i * 128;
        int r = idx >> 4;
        int c = (idx & 15) * 4;
        float4 v = *(const float4*)(Qp + base + (size_t)(q0 + r) * HID + c);
        float4 o;
        o.x = __uint_as_float(f2tf32(v.x * 0.125f));
        o.y = __uint_as_float(f2tf32(v.y * 0.125f));
        o.z = __uint_as_float(f2tf32(v.z * 0.125f));
        o.w = __uint_as_float(f2tf32(v.w * 0.125f));
        *(float4*)(&sm[r * AST + c]) = o;
    }

    auto load_kv = [&](int kb, int st) {
        const float* Kg = Kp + base + (size_t)kb * QBLK * HID;
        const float* Vg = Vp + base + (size_t)kb * QBLK * HID;
        #pragma unroll
        for (int i = 0; i < 8; i++) {
            int idx = tid + i * 128;
            int r = idx >> 4;
            int c = (idx & 15) * 4;
            uint32_t dk = smem_u32(&sm[OFF_K + st * 64 * AST + r * AST + c]);
            uint32_t dv = smem_u32(&sm[OFF_V + st * 64 * AST + r * AST + c]);
            asm volatile("cp.async.cg.shared.global [%0], [%1], 16;"
                         :: "r"(dk), "l"(Kg + (size_t)r * HID + c));
            asm volatile("cp.async.cg.shared.global [%0], [%1], 16;"
                         :: "r"(dv), "l"(Vg + (size_t)r * HID + c));
        }
        asm volatile("cp.async.commit_group;");
    };

    load_kv(0, 0);

    float m0r = -1e30f, m1r = -1e30f, l0 = 0.f, l1 = 0.f;
    float oacc[8][4];
    #pragma unroll
    for (int nt = 0; nt < 8; nt++)
        #pragma unroll
        for (int r = 0; r < 4; r++) oacc[nt][r] = 0.f;

    const int mrow = 16 * wid;   // warp's q-slice (S) / d-slice (PV)

    for (int kb = 0; kb <= qb; kb++) {
        const int s = kb & 1;
        asm volatile("cp.async.wait_group 0;");
        __syncthreads();
        if (kb + 1 <= qb) load_kv(kb + 1, s ^ 1);

        const float* Kst = sm + OFF_K + s * 64 * AST;
        const float* Vst = sm + OFF_V + s * 64 * AST;

        // ---- S = Q @ K^T ----
        float sacc[8][4];
        #pragma unroll
        for (int nt = 0; nt < 8; nt++)
            #pragma unroll
            for (int r = 0; r < 4; r++) sacc[nt][r] = 0.f;

        #pragma unroll
        for (int k8 = 0; k8 < 64; k8 += 8) {
            uint32_t a0 = __float_as_uint(sm[(mrow + g    ) * AST + k8 + t    ]);
            uint32_t a1 = __float_as_uint(sm[(mrow + g + 8) * AST + k8 + t    ]);
            uint32_t a2 = __float_as_uint(sm[(mrow + g    ) * AST + k8 + t + 4]);
            uint32_t a3 = __float_as_uint(sm[(mrow + g + 8) * AST + k8 + t + 4]);
            #pragma unroll
            for (int nt = 0; nt < 8; nt++) {
                uint32_t b0 = f2tf32(Kst[(nt * 8 + g) * AST + k8 + t    ]);
                uint32_t b1 = f2tf32(Kst[(nt * 8 + g) * AST + k8 + t + 4]);
                mma_tf32(sacc[nt][0], sacc[nt][1], sacc[nt][2], sacc[nt][3],
                         a0, a1, a2, a3, b0, b1);
            }
        }

        // ---- online softmax (rows mrow+g, mrow+g+8) ----
        float mx0 = -1e30f, mx1 = -1e30f;
        #pragma unroll
        for (int nt = 0; nt < 8; nt++) {
            mx0 = fmaxf(mx0, fmaxf(sacc[nt][0], sacc[nt][1]));
            mx1 = fmaxf(mx1, fmaxf(sacc[nt][2], sacc[nt][3]));
        }
        mx0 = fmaxf(mx0, __shfl_xor_sync(0xffffffffu, mx0, 1));
        mx0 = fmaxf(mx0, __shfl_xor_sync(0xffffffffu, mx0, 2));
        mx1 = fmaxf(mx1, __shfl_xor_sync(0xffffffffu, mx1, 1));
        mx1 = fmaxf(mx1, __shfl_xor_sync(0xffffffffu, mx1, 2));

        float mn0 = fmaxf(m0r, mx0), mn1 = fmaxf(m1r, mx1);
        float cr0 = fexp(m0r - mn0), cr1 = fexp(m1r - mn1);
        m0r = mn0; m1r = mn1;

        float s0 = 0.f, s1 = 0.f;
        #pragma unroll
        for (int nt = 0; nt < 8; nt++) {
            float p00 = fexp(sacc[nt][0] - mn0);
            float p01 = fexp(sacc[nt][1] - mn0);
            float p10 = fexp(sacc[nt][2] - mn1);
            float p11 = fexp(sacc[nt][3] - mn1);
            s0 += p00 + p01;
            s1 += p10 + p11;
            float2 w0 = { __uint_as_float(f2tf32(p00)), __uint_as_float(f2tf32(p01)) };
            float2 w1 = { __uint_as_float(f2tf32(p10)), __uint_as_float(f2tf32(p11)) };
            *(float2*)(&sm[OFF_P + (mrow + g    ) * AST + nt * 8 + 2 * t]) = w0;
            *(float2*)(&sm[OFF_P + (mrow + g + 8) * AST + nt * 8 + 2 * t]) = w1;
        }
        s0 += __shfl_xor_sync(0xffffffffu, s0, 1);
        s0 += __shfl_xor_sync(0xffffffffu, s0, 2);
        s1 += __shfl_xor_sync(0xffffffffu, s1, 1);
        s1 += __shfl_xor_sync(0xffffffffu, s1, 2);
        l0 = l0 * cr0 + s0;
        l1 = l1 * cr1 + s1;
        if (t == 0) {
            sm[OFF_CR + mrow + g    ] = cr0;
            sm[OFF_CR + mrow + g + 8] = cr1;
        }
        __syncthreads();

        // ---- O^T rescale by per-q corr, then O^T += V^T @ P^T ----
        #pragma unroll
        for (int nt = 0; nt < 8; nt++) {
            float cc0 = sm[OFF_CR + nt * 8 + 2 * t];
            float cc1 = sm[OFF_CR + nt * 8 + 2 * t + 1];
            oacc[nt][0] *= cc0; oacc[nt][1] *= cc1;
            oacc[nt][2] *= cc0; oacc[nt][3] *= cc1;
        }
        #pragma unroll
        for (int k8 = 0; k8 < 64; k8 += 8) {
            uint32_t a0 = f2tf32(Vst[(k8 + t    ) * AST + mrow + g    ]);
            uint32_t a1 = f2tf32(Vst[(k8 + t    ) * AST + mrow + g + 8]);
            uint32_t a2 = f2tf32(Vst[(k8 + t + 4) * AST + mrow + g    ]);
            uint32_t a3 = f2tf32(Vst[(k8 + t + 4) * AST + mrow + g + 8]);
            #pragma unroll
            for (int nt = 0; nt < 8; nt++) {
                uint32_t b0 = __float_as_uint(sm[OFF_P + (nt * 8 + g) * AST + k8 + t    ]);
                uint32_t b1 = __float_as_uint(sm[OFF_P + (nt * 8 + g) * AST + k8 + t + 4]);
                mma_tf32(oacc[nt][0], oacc[nt][1], oacc[nt][2], oacc[nt][3],
                         a0, a1, a2, a3, b0, b1);
            }
        }
    }

    // Epilogue: O[q][d] = O^T / l
    if (t == 0) {
        sm[OFF_LI + mrow + g    ] = 1.f / l0;
        sm[OFF_LI + mrow + g + 8] = 1.f / l1;
    }
    __syncthreads();
    #pragma unroll
    for (int nt = 0; nt < 8; nt++) {
        int q = nt * 8 + 2 * t;
        float li0 = sm[OFF_LI + q];
        float li1 = sm[OFF_LI + q + 1];
        float* O0 = Op + base + (size_t)(q0 + q) * HID + mrow;
        float* O1 = Op + base + (size_t)(q0 + q + 1) * HID + mrow;
        O0[g    ] = oacc[nt][0] * li0;
        O1[g    ] = oacc[nt][1] * li1;
        O0[g + 8] = oacc[nt][2] * li0;
        O1[g + 8] = oacc[nt][3] * li1;
    }
}

// ---------------------------------------------------------------------------

extern "C" void kernel_launch(void* const* d_in, const int* in_sizes, int n_in,
                              void* d_out, int out_size)
{
    (void)in_sizes; (void)n_in; (void)out_size;

    const float* X  = (const float*)d_in[0];
    const float* Wq = (const float*)d_in[1];
    const float* bq = (const float*)d_in[2];
    const float* Wk = (const float*)d_in[3];
    const float* bk = (const float*)d_in[4];
    const float* Wv = (const float*)d_in[5];
    const float* bv = (const float*)d_in[6];
    const float* Wo = (const float*)d_in[7];
    const float* bo = (const float*)d_in[8];

    float *Q, *K, *V, *A;
    cudaGetSymbolAddress((void**)&Q, g_Q);
    cudaGetSymbolAddress((void**)&K, g_K);
    cudaGetSymbolAddress((void**)&V, g_V);
    cudaGetSymbolAddress((void**)&A, g_A);

    dim3 gg(HID / TN, M_TOT / TM);   // (8, 32)

    gemm_tc<<<gg, 256>>>(X, Wq, bq, Q, M_TOT, HID, HID);
    gemm_tc<<<gg, 256>>>(X, Wk, bk, K, M_TOT, HID, HID);
    gemm_tc<<<gg, 256>>>(X, Wv, bv, V, M_TOT, HID, HID);

    cudaFuncSetAttribute(attn_tc,
                         cudaFuncAttributeMaxDynamicSharedMemorySize, ATT_SMEM);
    attn_tc<<<dim3(SEQ / QBLK, HEADS, BSZ), 128, ATT_SMEM>>>(Q, K, V, A);

    gemm_tc<<<gg, 256>>>(A, Wo, bo, (float*)d_out, M_TOT, HID, HID);
}

// round 12
// speedup vs baseline: 3.6163x; 1.3140x over previous
#include <cuda_runtime.h>
#include <cstdint>
#include <math.h>

#define BSZ   2
#define SEQ   2048
#define HID   1024
#define HEADS 16
#define HD    64
#define QBLK  64
#define M_TOT (BSZ*SEQ)

// Scratch (allocation-free)
__device__ float g_Q[(size_t)M_TOT * HID];
__device__ float g_K[(size_t)M_TOT * HID];
__device__ float g_V[(size_t)M_TOT * HID];
__device__ float g_A[(size_t)M_TOT * HID];
__device__ float g_X[(size_t)M_TOT * HID];      // tf32-rounded input
__device__ float g_W[4 * (size_t)HID * HID];    // tf32-rounded weights

__device__ __forceinline__ uint32_t smem_u32(const void* p) {
    uint32_t a;
    asm("{ .reg .u64 t; cvta.to.shared.u64 t, %1; cvt.u32.u64 %0, t; }"
        : "=r"(a) : "l"(p));
    return a;
}

__device__ __forceinline__ uint32_t f2tf32(float v) {
    uint32_t r;
    asm("cvt.rna.tf32.f32 %0, %1;" : "=r"(r) : "f"(v));
    return r;
}

__device__ __forceinline__ void ldsm4(uint32_t& r0, uint32_t& r1,
                                      uint32_t& r2, uint32_t& r3, uint32_t a) {
    asm volatile("ldmatrix.sync.aligned.m8n8.x4.shared.b16 {%0,%1,%2,%3}, [%4];"
                 : "=r"(r0), "=r"(r1), "=r"(r2), "=r"(r3) : "r"(a));
}

__device__ __forceinline__ void mma_tf32(
    float& c0, float& c1, float& c2, float& c3,
    uint32_t a0, uint32_t a1, uint32_t a2, uint32_t a3,
    uint32_t b0, uint32_t b1)
{
    asm volatile(
        "mma.sync.aligned.m16n8k8.row.col.f32.tf32.tf32.f32 "
        "{%0,%1,%2,%3}, {%4,%5,%6,%7}, {%8,%9}, {%0,%1,%2,%3};"
        : "+f"(c0), "+f"(c1), "+f"(c2), "+f"(c3)
        : "r"(a0), "r"(a1), "r"(a2), "r"(a3), "r"(b0), "r"(b1));
}

// Fast exp on FMA/ALU pipes (no MUFU).
__device__ __forceinline__ float fexp(float x) {
    x = fmaxf(x, -87.0f);
    float y = x * 1.44269504088896f;
    float z = y + 12582912.0f;
    float i = z - 12582912.0f;
    float f = y - i;
    float p =            1.33335581e-3f;
    p = fmaf(p, f, 9.61812911e-3f);
    p = fmaf(p, f, 5.55041087e-2f);
    p = fmaf(p, f, 2.40226507e-1f);
    p = fmaf(p, f, 6.93147181e-1f);
    p = fmaf(p, f, 1.0f);
    float sc = __int_as_float((__float_as_int(z) << 23) + 0x3f800000);
    return sc * p;
}

// ===========================================================================
// Pre-round passes (tf32-round inputs once; removes all CVT from hot loops)
// ===========================================================================
__global__ __launch_bounds__(256) void round_x_k(const float4* __restrict__ s,
                                                 float4* __restrict__ d) {
    int i = blockIdx.x * 256 + threadIdx.x;
    float4 v = s[i];
    v.x = __uint_as_float(f2tf32(v.x));
    v.y = __uint_as_float(f2tf32(v.y));
    v.z = __uint_as_float(f2tf32(v.z));
    v.w = __uint_as_float(f2tf32(v.w));
    d[i] = v;
}

__global__ __launch_bounds__(256) void round_w_k(
    const float* __restrict__ w0, const float* __restrict__ w1,
    const float* __restrict__ w2, const float* __restrict__ w3,
    float* __restrict__ dst)
{
    int z = blockIdx.z;
    const float4* s = (const float4*)(z == 0 ? w0 : z == 1 ? w1 : z == 2 ? w2 : w3);
    float4* d = (float4*)(dst + (size_t)z * HID * HID);
    int i = blockIdx.x * 256 + threadIdx.x;
    float4 v = s[i];
    v.x = __uint_as_float(f2tf32(v.x));
    v.y = __uint_as_float(f2tf32(v.y));
    v.z = __uint_as_float(f2tf32(v.z));
    v.w = __uint_as_float(f2tf32(v.w));
    d[i] = v;
}

// ===========================================================================
// HMMA tf32 GEMM, pre-rounded inputs, ldmatrix fragments, no CVT.
// C = A@W^T + bias. grid.z selects (W, bias, C) -> fused QKV in one launch.
// round_out=1 writes tf32-rounded results (QKV / attn-side consumers).
// ===========================================================================
#define TM 128
#define TN 128
#define BK 16
#define SPAD 20

__global__ __launch_bounds__(256) void gemm_tc(
    const float* __restrict__ A,
    const float* __restrict__ W0, const float* __restrict__ W1,
    const float* __restrict__ W2,
    const float* __restrict__ b0p, const float* __restrict__ b1p,
    const float* __restrict__ b2p,
    float* __restrict__ C0, float* __restrict__ C1, float* __restrict__ C2,
    int round_out)
{
    __shared__ __align__(16) float As[2][TM][SPAD];
    __shared__ __align__(16) float Bs[2][TN][SPAD];

    const int z = blockIdx.z;
    const float* B    = z == 0 ? W0 : z == 1 ? W1 : W2;
    const float* bias = z == 0 ? b0p : z == 1 ? b1p : b2p;
    float*       C    = z == 0 ? C0 : z == 1 ? C1 : C2;

    const int tid  = threadIdx.x;
    const int wid  = tid >> 5;
    const int lane = tid & 31;
    const int g    = lane >> 2;
    const int t    = lane & 3;
    const int m0   = blockIdx.y * TM;
    const int n0   = blockIdx.x * TN;
    const int moff = (wid & 1) * 64;
    const int noff = (wid >> 1) * 32;
    const int NK   = HID / BK;

    const int lr = tid >> 2;
    const int lc = (tid & 3) * 4;

    const float* Ab = A + (size_t)m0 * HID;
    const float* Bb = B + (size_t)n0 * HID;

    // ldmatrix lane bases
    const int q8 = lane >> 3;
    const int r8 = lane & 7;
    const uint32_t uA = smem_u32(As);
    const uint32_t uB = smem_u32(Bs);
    // A-frag: row = moff + (q&1)*8 + r, col = (q>>1)*4
    const uint32_t aLane = ((moff + (q8 & 1) * 8 + r8) * SPAD + (q8 >> 1) * 4) * 4;
    // B-pair: row_add = (q>>1)*8 + r, col = (q&1)*4
    const uint32_t bLane = (((q8 >> 1) * 8 + r8) * SPAD + (q8 & 1) * 4) * 4;

    float acc[4][4][4];
    #pragma unroll
    for (int i = 0; i < 4; i++)
        #pragma unroll
        for (int j = 0; j < 4; j++)
            #pragma unroll
            for (int r = 0; r < 4; r++) acc[i][j][r] = 0.f;

    auto load_stage = [&](int kc, int s) {
        const float* Ag = Ab + kc * BK;
        const float* Bg = Bb + kc * BK;
        #pragma unroll
        for (int i = 0; i < 2; i++) {
            int r = lr + i * 64;
            uint32_t da = smem_u32(&As[s][r][lc]);
            uint32_t db = smem_u32(&Bs[s][r][lc]);
            asm volatile("cp.async.cg.shared.global [%0], [%1], 16;"
                         :: "r"(da), "l"(Ag + (size_t)r * HID + lc));
            asm volatile("cp.async.cg.shared.global [%0], [%1], 16;"
                         :: "r"(db), "l"(Bg + (size_t)r * HID + lc));
        }
        asm volatile("cp.async.commit_group;");
    };

    load_stage(0, 0);

    for (int kc = 0; kc < NK; kc++) {
        const int s = kc & 1;
        if (kc + 1 < NK) {
            load_stage(kc + 1, s ^ 1);
            asm volatile("cp.async.wait_group 1;");
        } else {
            asm volatile("cp.async.wait_group 0;");
        }
        __syncthreads();

        const uint32_t sA = uA + (uint32_t)(s * TM * SPAD * 4);
        const uint32_t sB = uB + (uint32_t)(s * TN * SPAD * 4);

        #pragma unroll
        for (int k8 = 0; k8 < BK; k8 += 8) {
            uint32_t a[4][4];
            #pragma unroll
            for (int mt = 0; mt < 4; mt++)
                ldsm4(a[mt][0], a[mt][1], a[mt][2], a[mt][3],
                      sA + aLane + (uint32_t)((mt * 16 * SPAD + k8) * 4));
            #pragma unroll
            for (int p = 0; p < 2; p++) {
                uint32_t b0, b1, b2, b3;
                ldsm4(b0, b1, b2, b3,
                      sB + bLane + (uint32_t)(((noff + p * 16) * SPAD + k8) * 4));
                #pragma unroll
                for (int mt = 0; mt < 4; mt++) {
                    mma_tf32(acc[mt][2*p][0], acc[mt][2*p][1],
                             acc[mt][2*p][2], acc[mt][2*p][3],
                             a[mt][0], a[mt][1], a[mt][2], a[mt][3], b0, b1);
                    mma_tf32(acc[mt][2*p+1][0], acc[mt][2*p+1][1],
                             acc[mt][2*p+1][2], acc[mt][2*p+1][3],
                             a[mt][0], a[mt][1], a[mt][2], a[mt][3], b2, b3);
                }
            }
        }
        __syncthreads();
    }

    #pragma unroll
    for (int mt = 0; mt < 4; mt++) {
        int mrow0 = m0 + moff + mt * 16 + g;
        #pragma unroll
        for (int nt = 0; nt < 4; nt++) {
            int n = n0 + noff + nt * 8 + 2 * t;
            float b0 = __ldg(bias + n);
            float b1 = __ldg(bias + n + 1);
            float v0 = acc[mt][nt][0] + b0, v1 = acc[mt][nt][1] + b1;
            float v2 = acc[mt][nt][2] + b0, v3 = acc[mt][nt][3] + b1;
            if (round_out) {
                v0 = __uint_as_float(f2tf32(v0));
                v1 = __uint_as_float(f2tf32(v1));
                v2 = __uint_as_float(f2tf32(v2));
                v3 = __uint_as_float(f2tf32(v3));
            }
            float2 w0 = { v0, v1 }, w1 = { v2, v3 };
            *(float2*)(C + (size_t)mrow0 * HID + n)       = w0;
            *(float2*)(C + (size_t)(mrow0 + 8) * HID + n) = w1;
        }
    }
}

// ===========================================================================
// Tensor-core flash attention; inputs pre-rounded tf32 -> no CVT in loop;
// ldmatrix for Q/K/P fragments; V scalar (transposed access).
// ===========================================================================
#define AST 68
#define OFF_K   (64*AST)
#define OFF_V   (3*64*AST)
#define OFF_P   (5*64*AST)
#define OFF_CR  (6*64*AST)
#define OFF_LI  (6*64*AST + 64)
#define ATT_SMEM ((6*64*AST + 128) * 4)

__global__ __launch_bounds__(128) void attn_tc(
    const float* __restrict__ Qp, const float* __restrict__ Kp,
    const float* __restrict__ Vp, float* __restrict__ Op)
{
    extern __shared__ __align__(16) float sm[];
    const int tid  = threadIdx.x;
    const int wid  = tid >> 5;
    const int lane = tid & 31;
    const int g    = lane >> 2;
    const int t    = lane & 3;
    const int q8   = lane >> 3;
    const int r8   = lane & 7;

    const int qb = (int)gridDim.x - 1 - (int)blockIdx.x;
    const int h  = blockIdx.y;
    const int b  = blockIdx.z;
    const int q0 = qb * QBLK;
    const size_t base = (size_t)b * SEQ * HID + (size_t)h * HD;

    // Load Q tile, scale by 1/8 (exact; values already tf32)
    #pragma unroll
    for (int i = 0; i < 8; i++) {
        int idx = tid + i * 128;
        int r = idx >> 4;
        int c = (idx & 15) * 4;
        float4 v = *(const float4*)(Qp + base + (size_t)(q0 + r) * HID + c);
        v.x *= 0.125f; v.y *= 0.125f; v.z *= 0.125f; v.w *= 0.125f;
        *(float4*)(&sm[r * AST + c]) = v;
    }

    auto load_kv = [&](int kb, int st) {
        const float* Kg = Kp + base + (size_t)kb * QBLK * HID;
        const float* Vg = Vp + base + (size_t)kb * QBLK * HID;
        #pragma unroll
        for (int i = 0; i < 8; i++) {
            int idx = tid + i * 128;
            int r = idx >> 4;
            int c = (idx & 15) * 4;
            uint32_t dk = smem_u32(&sm[OFF_K + st * 64 * AST + r * AST + c]);
            uint32_t dv = smem_u32(&sm[OFF_V + st * 64 * AST + r * AST + c]);
            asm volatile("cp.async.cg.shared.global [%0], [%1], 16;"
                         :: "r"(dk), "l"(Kg + (size_t)r * HID + c));
            asm volatile("cp.async.cg.shared.global [%0], [%1], 16;"
                         :: "r"(dv), "l"(Vg + (size_t)r * HID + c));
        }
        asm volatile("cp.async.commit_group;");
    };

    load_kv(0, 0);

    float m0r = -1e30f, m1r = -1e30f, l0 = 0.f, l1 = 0.f;
    float oacc[8][4];
    #pragma unroll
    for (int nt = 0; nt < 8; nt++)
        #pragma unroll
        for (int r = 0; r < 4; r++) oacc[nt][r] = 0.f;

    const int mrow = 16 * wid;
    const uint32_t uS = smem_u32(sm);
    // a-frag lane base (Q): row = mrow + (q&1)*8 + r, col = (q>>1)*4
    const uint32_t qLane = uS + ((mrow + (q8 & 1) * 8 + r8) * AST + (q8 >> 1) * 4) * 4;
    // b-pair lane base (K/P): row_add = (q>>1)*8 + r, col = (q&1)*4
    const uint32_t bLane = (((q8 >> 1) * 8 + r8) * AST + (q8 & 1) * 4) * 4;

    for (int kb = 0; kb <= qb; kb++) {
        const int s = kb & 1;
        asm volatile("cp.async.wait_group 0;");
        __syncthreads();
        if (kb + 1 <= qb) load_kv(kb + 1, s ^ 1);

        const float* Vst = sm + OFF_V + s * 64 * AST;
        const uint32_t kBase = uS + (uint32_t)((OFF_K + s * 64 * AST) * 4) + bLane;
        const uint32_t pBase = uS + (uint32_t)(OFF_P * 4) + bLane;

        // ---- S = Q @ K^T ----
        float sacc[8][4];
        #pragma unroll
        for (int nt = 0; nt < 8; nt++)
            #pragma unroll
            for (int r = 0; r < 4; r++) sacc[nt][r] = 0.f;

        #pragma unroll
        for (int k8 = 0; k8 < 64; k8 += 8) {
            uint32_t a0, a1, a2, a3;
            ldsm4(a0, a1, a2, a3, qLane + (uint32_t)(k8 * 4));
            #pragma unroll
            for (int p = 0; p < 4; p++) {
                uint32_t b0, b1, b2, b3;
                ldsm4(b0, b1, b2, b3, kBase + (uint32_t)((p * 16 * AST + k8) * 4));
                mma_tf32(sacc[2*p][0], sacc[2*p][1], sacc[2*p][2], sacc[2*p][3],
                         a0, a1, a2, a3, b0, b1);
                mma_tf32(sacc[2*p+1][0], sacc[2*p+1][1], sacc[2*p+1][2], sacc[2*p+1][3],
                         a0, a1, a2, a3, b2, b3);
            }
        }

        // ---- online softmax ----
        float mx0 = -1e30f, mx1 = -1e30f;
        #pragma unroll
        for (int nt = 0; nt < 8; nt++) {
            mx0 = fmaxf(mx0, fmaxf(sacc[nt][0], sacc[nt][1]));
            mx1 = fmaxf(mx1, fmaxf(sacc[nt][2], sacc[nt][3]));
        }
        mx0 = fmaxf(mx0, __shfl_xor_sync(0xffffffffu, mx0, 1));
        mx0 = fmaxf(mx0, __shfl_xor_sync(0xffffffffu, mx0, 2));
        mx1 = fmaxf(mx1, __shfl_xor_sync(0xffffffffu, mx1, 1));
        mx1 = fmaxf(mx1, __shfl_xor_sync(0xffffffffu, mx1, 2));

        float mn0 = fmaxf(m0r, mx0), mn1 = fmaxf(m1r, mx1);
        float cr0 = fexp(m0r - mn0), cr1 = fexp(m1r - mn1);
        m0r = mn0; m1r = mn1;

        float s0 = 0.f, s1 = 0.f;
        #pragma unroll
        for (int nt = 0; nt < 8; nt++) {
            float p00 = fexp(sacc[nt][0] - mn0);
            float p01 = fexp(sacc[nt][1] - mn0);
            float p10 = fexp(sacc[nt][2] - mn1);
            float p11 = fexp(sacc[nt][3] - mn1);
            s0 += p00 + p01;
            s1 += p10 + p11;
            float2 w0 = { __uint_as_float(f2tf32(p00)), __uint_as_float(f2tf32(p01)) };
            float2 w1 = { __uint_as_float(f2tf32(p10)), __uint_as_float(f2tf32(p11)) };
            *(float2*)(&sm[OFF_P + (mrow + g    ) * AST + nt * 8 + 2 * t]) = w0;
            *(float2*)(&sm[OFF_P + (mrow + g + 8) * AST + nt * 8 + 2 * t]) = w1;
        }
        s0 += __shfl_xor_sync(0xffffffffu, s0, 1);
        s0 += __shfl_xor_sync(0xffffffffu, s0, 2);
        s1 += __shfl_xor_sync(0xffffffffu, s1, 1);
        s1 += __shfl_xor_sync(0xffffffffu, s1, 2);
        l0 = l0 * cr0 + s0;
        l1 = l1 * cr1 + s1;
        if (t == 0) {
            sm[OFF_CR + mrow + g    ] = cr0;
            sm[OFF_CR + mrow + g + 8] = cr1;
        }
        __syncthreads();

        // ---- O^T rescale, then O^T += V^T @ P^T ----
        #pragma unroll
        for (int nt = 0; nt < 8; nt++) {
            float cc0 = sm[OFF_CR + nt * 8 + 2 * t];
            float cc1 = sm[OFF_CR + nt * 8 + 2 * t + 1];
            oacc[nt][0] *= cc0; oacc[nt][1] *= cc1;
            oacc[nt][2] *= cc0; oacc[nt][3] *= cc1;
        }
        #pragma unroll
        for (int k8 = 0; k8 < 64; k8 += 8) {
            uint32_t a0 = __float_as_uint(Vst[(k8 + t    ) * AST + mrow + g    ]);
            uint32_t a1 = __float_as_uint(Vst[(k8 + t    ) * AST + mrow + g + 8]);
            uint32_t a2 = __float_as_uint(Vst[(k8 + t + 4) * AST + mrow + g    ]);
            uint32_t a3 = __float_as_uint(Vst[(k8 + t + 4) * AST + mrow + g + 8]);
            #pragma unroll
            for (int p = 0; p < 4; p++) {
                uint32_t b0, b1, b2, b3;
                ldsm4(b0, b1, b2, b3, pBase + (uint32_t)((p * 16 * AST + k8) * 4));
                mma_tf32(oacc[2*p][0], oacc[2*p][1], oacc[2*p][2], oacc[2*p][3],
                         a0, a1, a2, a3, b0, b1);
                mma_tf32(oacc[2*p+1][0], oacc[2*p+1][1], oacc[2*p+1][2], oacc[2*p+1][3],
                         a0, a1, a2, a3, b2, b3);
            }
        }
    }

    // Epilogue: O[q][d] = O^T / l  (rounded to tf32 for the final GEMM)
    if (t == 0) {
        sm[OFF_LI + mrow + g    ] = 1.f / l0;
        sm[OFF_LI + mrow + g + 8] = 1.f / l1;
    }
    __syncthreads();
    #pragma unroll
    for (int nt = 0; nt < 8; nt++) {
        int q = nt * 8 + 2 * t;
        float li0 = sm[OFF_LI + q];
        float li1 = sm[OFF_LI + q + 1];
        float* O0 = Op + base + (size_t)(q0 + q) * HID + mrow;
        float* O1 = Op + base + (size_t)(q0 + q + 1) * HID + mrow;
        O0[g    ] = __uint_as_float(f2tf32(oacc[nt][0] * li0));
        O1[g    ] = __uint_as_float(f2tf32(oacc[nt][1] * li1));
        O0[g + 8] = __uint_as_float(f2tf32(oacc[nt][2] * li0));
        O1[g + 8] = __uint_as_float(f2tf32(oacc[nt][3] * li1));
    }
}

// ---------------------------------------------------------------------------

extern "C" void kernel_launch(void* const* d_in, const int* in_sizes, int n_in,
                              void* d_out, int out_size)
{
    (void)in_sizes; (void)n_in; (void)out_size;

    const float* X  = (const float*)d_in[0];
    const float* Wq = (const float*)d_in[1];
    const float* bq = (const float*)d_in[2];
    const float* Wk = (const float*)d_in[3];
    const float* bk = (const float*)d_in[4];
    const float* Wv = (const float*)d_in[5];
    const float* bv = (const float*)d_in[6];
    const float* Wo = (const float*)d_in[7];
    const float* bo = (const float*)d_in[8];

    float *Q, *K, *V, *A, *Xr, *Wr;
    cudaGetSymbolAddress((void**)&Q,  g_Q);
    cudaGetSymbolAddress((void**)&K,  g_K);
    cudaGetSymbolAddress((void**)&V,  g_V);
    cudaGetSymbolAddress((void**)&A,  g_A);
    cudaGetSymbolAddress((void**)&Xr, g_X);
    cudaGetSymbolAddress((void**)&Wr, g_W);

    const size_t WSZ = (size_t)HID * HID;

    // 1. pre-round inputs to tf32
    round_x_k<<<M_TOT * HID / 4 / 256, 256>>>((const float4*)X, (float4*)Xr);
    round_w_k<<<dim3(WSZ / 4 / 256, 1, 4), 256>>>(Wq, Wk, Wv, Wo, Wr);

    // 2. fused QKV projection
    dim3 gq(HID / TN, M_TOT / TM, 3);
    gemm_tc<<<gq, 256>>>(Xr, Wr, Wr + WSZ, Wr + 2 * WSZ,
                         bq, bk, bv, Q, K, V, 1);

    // 3. attention
    cudaFuncSetAttribute(attn_tc,
                         cudaFuncAttributeMaxDynamicSharedMemorySize, ATT_SMEM);
    attn_tc<<<dim3(SEQ / QBLK, HEADS, BSZ), 128, ATT_SMEM>>>(Q, K, V, A);

    // 4. output projection
    dim3 go(HID / TN, M_TOT / TM, 1);
    gemm_tc<<<go, 256>>>(A, Wr + 3 * WSZ, Wr + 3 * WSZ, Wr + 3 * WSZ,
                         bo, bo, bo,
                         (float*)d_out, (float*)d_out, (float*)d_out, 0);
}